// round 3
// baseline (speedup 1.0000x reference)
#include <cuda_runtime.h>
#include <math.h>

#define DD 196
#define SEQ 65
#define NCH 64
#define NH 8
#define DH 64
#define INNER 512
#define MLP 784

// Scratch (allocation-free, __device__ globals)
__device__ float g_xatt[SEQ * DD];
__device__ float g_qkv[SEQ * 3 * INNER];
__device__ float g_o[SEQ * INNER];
__device__ float g_x2[SEQ * DD];
__device__ float g_ff[SEQ * MLP];

// ---------------------------------------------------------------------------
// Gate path (device function, run by one block):
// conv1d+BN+ReLU -> sort-based gating -> FC -> sigmoid -> x_att
// ---------------------------------------------------------------------------
__device__ void gate_block(const float* __restrict__ x_pe, const float* __restrict__ tokens,
                           const float* __restrict__ conv_k,
                           const float* __restrict__ bn_g, const float* __restrict__ bn_b,
                           const float* __restrict__ bn_rm, const float* __restrict__ bn_rv,
                           const float* __restrict__ fc_w1, const float* __restrict__ fc_w2) {
    __shared__ float b1s[NCH];
    __shared__ float b2s[NCH];
    __shared__ float csm[NCH];
    __shared__ float hid[12];

    int t = threadIdx.x;
    int w = t >> 5, l = t & 31;

    float km0 = conv_k[3], km1 = conv_k[4], km2 = conv_k[5];  // conv_k[1][*]
    float s = bn_g[0] * rsqrtf(bn_rv[0] + 1e-5f);
    float bias = bn_b[0] - bn_rm[0] * s;

    for (int ch = w; ch < NCH; ch += 8) {
        const float* row = x_pe + ch * DD;
        float sum = 0.f;
        for (int i = l; i < DD; i += 32) {
            float left  = (i > 0)      ? row[i - 1] : 0.f;
            float mid   = row[i];
            float right = (i < DD - 1) ? row[i + 1] : 0.f;
            float conv = km0 * left + km1 * mid + km2 * right;
            float a = fmaxf(conv * s + bias, 0.f);
            g_xatt[ch * DD + i] = a;
            sum += a;
        }
        #pragma unroll
        for (int o = 16; o; o >>= 1) sum += __shfl_xor_sync(0xffffffffu, sum, o);
        if (l == 0) b1s[ch] = sum * (1.f / DD);
    }
    __syncthreads();

    if (t < NCH) {
        float v = b1s[t];
        int rank = 0, cnt = 0;
        float mx = -1e30f, mn = 1e30f;
        for (int j = 0; j < NCH; j++) {
            float u = b1s[j];
            rank += (u < v) || (u == v && j < t);
            cnt += (u <= 0.f);
            mx = fmaxf(mx, u);
            mn = fminf(mn, u);
        }
        int middle = (cnt == NCH) ? 0 : cnt;
        if (mx < 0.f || mn > 0.f) middle = 32;
        float ls = (float)middle, le = (float)(NCH - middle);
        float o;
        if (rank < middle) o = v - 1.f / (1.f + powf(ls, v));
        else               o = v + 1.f / (1.f + powf(le, -v));
        b2s[t] = o;
    }
    __syncthreads();

    if (t < 12) {
        float acc = 0.f;
        for (int c = 0; c < NCH; c++) acc += b2s[c] * fc_w1[c * 12 + t];
        hid[t] = fmaxf(acc, 0.f);
    }
    __syncthreads();

    if (t < NCH) {
        float acc = 0.f;
        #pragma unroll
        for (int k = 0; k < 12; k++) acc += hid[k] * fc_w2[k * NCH + t];
        csm[t] = 1.f / (1.f + expf(-acc));
    }
    __syncthreads();

    for (int i = t; i < NCH * DD; i += 256) g_xatt[i] *= csm[i / DD];
    for (int i = t; i < DD; i += 256) g_xatt[NCH * DD + i] = tokens[i];
}

// ---------------------------------------------------------------------------
// In-block LayerNorm over a 5-row tile held in smem. 256 threads.
// ---------------------------------------------------------------------------
__device__ __forceinline__ void ln_tile(const float* __restrict__ xs,
                                        float* __restrict__ hs,
                                        const float* __restrict__ g,
                                        const float* __restrict__ b,
                                        float* __restrict__ smean,
                                        float* __restrict__ sinv) {
    int t = threadIdx.x, w = t >> 5, l = t & 31;
    if (w < 5) {
        float sum = 0.f, sq = 0.f;
        for (int i = l; i < DD; i += 32) {
            float v = xs[w * DD + i];
            sum += v; sq += v * v;
        }
        #pragma unroll
        for (int o = 16; o; o >>= 1) {
            sum += __shfl_xor_sync(0xffffffffu, sum, o);
            sq  += __shfl_xor_sync(0xffffffffu, sq, o);
        }
        if (l == 0) {
            float mean = sum * (1.f / DD);
            float var = sq * (1.f / DD) - mean * mean;
            smean[w] = mean;
            sinv[w] = rsqrtf(var + 1e-5f);
        }
    }
    __syncthreads();
    for (int i = t; i < 5 * DD; i += 256) {
        int r = i / DD, c = i - r * DD;
        hs[i] = (xs[i] - smean[r]) * sinv[r] * g[c] + b[c];
    }
    __syncthreads();
}

// ---------------------------------------------------------------------------
// Fused: blocks 0..77 do LN1 + QKV GEMM (13 row-tiles x 6 col-chunks);
// block 78 does the gate path.
// ---------------------------------------------------------------------------
__global__ void __launch_bounds__(256) k_qkv_gate(
        const float* __restrict__ x, const float* __restrict__ ln_g,
        const float* __restrict__ ln_b, const float* __restrict__ w,
        const float* __restrict__ x_pe, const float* __restrict__ tokens,
        const float* __restrict__ conv_k,
        const float* __restrict__ bn_g, const float* __restrict__ bn_b,
        const float* __restrict__ bn_rm, const float* __restrict__ bn_rv,
        const float* __restrict__ fc_w1, const float* __restrict__ fc_w2) {
    if (blockIdx.x == 78) {
        gate_block(x_pe, tokens, conv_k, bn_g, bn_b, bn_rm, bn_rv, fc_w1, fc_w2);
        return;
    }
    __shared__ float xs[5 * DD];
    __shared__ float hs[5 * DD];
    __shared__ float smean[5], sinv[5];
    int bx = blockIdx.x / 6, by = blockIdx.x % 6;
    int r0 = bx * 5;
    int col = by * 256 + threadIdx.x;  // always < 1536
    for (int i = threadIdx.x; i < 5 * DD; i += 256) xs[i] = x[r0 * DD + i];
    __syncthreads();
    ln_tile(xs, hs, ln_g, ln_b, smean, sinv);
    float acc[5] = {0.f, 0.f, 0.f, 0.f, 0.f};
    #pragma unroll 14
    for (int k = 0; k < DD; k++) {
        float wv = w[k * 1536 + col];
        #pragma unroll
        for (int r = 0; r < 5; r++) acc[r] += hs[r * DD + k] * wv;
    }
    #pragma unroll
    for (int r = 0; r < 5; r++) g_qkv[(r0 + r) * 1536 + col] = acc[r];
}

// ---------------------------------------------------------------------------
// Attention: grid (13 row-tiles, 8 heads), 160 threads.
// ---------------------------------------------------------------------------
__global__ void k_attn() {
    __shared__ float skT[DH * 67];       // [d][j]
    __shared__ float sv[SEQ * DH];       // [j][d]
    __shared__ float sq[5 * DH];
    __shared__ float sp[5 * 66];
    int h = blockIdx.y, r0 = blockIdx.x * 5;
    int t = threadIdx.x;

    for (int i = t; i < SEQ * DH; i += 160) {
        int j = i >> 6, d = i & 63;
        skT[d * 67 + j] = g_qkv[j * 1536 + INNER + h * 64 + d];
        sv[i]           = g_qkv[j * 1536 + 2 * INNER + h * 64 + d];
    }
    for (int i = t; i < 5 * DH; i += 160) {
        int r = i >> 6, d = i & 63;
        sq[i] = g_qkv[(r0 + r) * 1536 + h * 64 + d];
    }
    __syncthreads();

    for (int e = t; e < 5 * SEQ; e += 160) {
        int i = e / SEQ, j = e - i * SEQ;
        float acc = 0.f;
        #pragma unroll
        for (int d = 0; d < DH; d++) acc += sq[i * 64 + d] * skT[d * 67 + j];
        sp[i * 66 + j] = acc * 0.125f;
    }
    __syncthreads();

    int w = t >> 5, l = t & 31;
    if (w < 5) {
        float mx = -1e30f;
        for (int j = l; j < SEQ; j += 32) mx = fmaxf(mx, sp[w * 66 + j]);
        #pragma unroll
        for (int o = 16; o; o >>= 1) mx = fmaxf(mx, __shfl_xor_sync(0xffffffffu, mx, o));
        float sum = 0.f;
        for (int j = l; j < SEQ; j += 32) {
            float p = expf(sp[w * 66 + j] - mx);
            sp[w * 66 + j] = p;
            sum += p;
        }
        #pragma unroll
        for (int o = 16; o; o >>= 1) sum += __shfl_xor_sync(0xffffffffu, sum, o);
        float inv = 1.f / sum;
        for (int j = l; j < SEQ; j += 32) sp[w * 66 + j] *= inv;
    }
    __syncthreads();

    for (int e = t; e < 5 * DH; e += 160) {
        int i = e >> 6, d = e & 63;
        float acc = 0.f;
        #pragma unroll 13
        for (int j = 0; j < SEQ; j++) acc += sp[i * 66 + j] * sv[j * 64 + d];
        g_o[(r0 + i) * INNER + h * 64 + d] = acc;
    }
}

// ---------------------------------------------------------------------------
// Out-proj + residuals: x2 = o @ w_out + b_out + x + x_att. grid 13, 256 thr
// ---------------------------------------------------------------------------
__global__ void __launch_bounds__(256) k_oproj(const float* __restrict__ w_out,
                                               const float* __restrict__ b_out,
                                               const float* __restrict__ x) {
    __shared__ float so[5 * INNER];
    int r0 = blockIdx.x * 5;
    for (int i = threadIdx.x; i < 5 * INNER; i += 256) so[i] = g_o[r0 * INNER + i];
    __syncthreads();
    int col = threadIdx.x;
    if (col < DD) {
        float acc[5] = {0.f, 0.f, 0.f, 0.f, 0.f};
        #pragma unroll 16
        for (int k = 0; k < INNER; k++) {
            float wv = w_out[k * DD + col];
            #pragma unroll
            for (int r = 0; r < 5; r++) acc[r] += so[r * INNER + k] * wv;
        }
        float bb = b_out[col];
        #pragma unroll
        for (int r = 0; r < 5; r++) {
            int row = r0 + r;
            g_x2[row * DD + col] = acc[r] + bb + x[row * DD + col] + g_xatt[row * DD + col];
        }
    }
}

// ---------------------------------------------------------------------------
// LN2 + FF1 + exact GELU: [65,196] @ [196,784]. grid (13, 4), 256 thr
// ---------------------------------------------------------------------------
__global__ void __launch_bounds__(256) k_ff1(const float* __restrict__ ln_g,
                                             const float* __restrict__ ln_b,
                                             const float* __restrict__ w1,
                                             const float* __restrict__ b1v) {
    __shared__ float xs[5 * DD];
    __shared__ float hs[5 * DD];
    __shared__ float smean[5], sinv[5];
    int r0 = blockIdx.x * 5;
    int col = blockIdx.y * 256 + threadIdx.x;
    for (int i = threadIdx.x; i < 5 * DD; i += 256) xs[i] = g_x2[r0 * DD + i];
    __syncthreads();
    ln_tile(xs, hs, ln_g, ln_b, smean, sinv);
    if (col < MLP) {
        float acc[5] = {0.f, 0.f, 0.f, 0.f, 0.f};
        #pragma unroll 14
        for (int k = 0; k < DD; k++) {
            float wv = w1[k * MLP + col];
            #pragma unroll
            for (int r = 0; r < 5; r++) acc[r] += hs[r * DD + k] * wv;
        }
        float bb = b1v[col];
        #pragma unroll
        for (int r = 0; r < 5; r++) {
            float v = acc[r] + bb;
            g_ff[(r0 + r) * MLP + col] = 0.5f * v * (1.f + erff(v * 0.70710678118654752f));
        }
    }
}

// ---------------------------------------------------------------------------
// FF2 + residual: out = g_ff @ w2 + b2 + x2. grid 13, 256 thr
// ---------------------------------------------------------------------------
__global__ void __launch_bounds__(256) k_ff2(const float* __restrict__ w2,
                                             const float* __restrict__ b2v,
                                             float* __restrict__ out) {
    __shared__ float sg[5 * MLP];
    int r0 = blockIdx.x * 5;
    for (int i = threadIdx.x; i < 5 * MLP; i += 256) sg[i] = g_ff[r0 * MLP + i];
    __syncthreads();
    int col = threadIdx.x;
    if (col < DD) {
        float acc[5] = {0.f, 0.f, 0.f, 0.f, 0.f};
        #pragma unroll 16
        for (int k = 0; k < MLP; k++) {
            float wv = w2[k * DD + col];
            #pragma unroll
            for (int r = 0; r < 5; r++) acc[r] += sg[r * MLP + k] * wv;
        }
        float bb = b2v[col];
        #pragma unroll
        for (int r = 0; r < 5; r++) {
            int row = r0 + r;
            out[row * DD + col] = acc[r] + bb + g_x2[row * DD + col];
        }
    }
}

// ---------------------------------------------------------------------------
extern "C" void kernel_launch(void* const* d_in, const int* in_sizes, int n_in,
                              void* d_out, int out_size) {
    const float* x      = (const float*)d_in[0];
    const float* tokens = (const float*)d_in[1];
    const float* x_pe   = (const float*)d_in[2];
    const float* conv_k = (const float*)d_in[3];
    const float* bn_g   = (const float*)d_in[4];
    const float* bn_b   = (const float*)d_in[5];
    const float* bn_rm  = (const float*)d_in[6];
    const float* bn_rv  = (const float*)d_in[7];
    const float* fc_w1  = (const float*)d_in[8];
    const float* fc_w2  = (const float*)d_in[9];
    const float* ln1_g  = (const float*)d_in[10];
    const float* ln1_b  = (const float*)d_in[11];
    const float* ln2_g  = (const float*)d_in[12];
    const float* ln2_b  = (const float*)d_in[13];
    const float* w_qkv  = (const float*)d_in[14];
    const float* w_out  = (const float*)d_in[15];
    const float* b_out  = (const float*)d_in[16];
    const float* ff_w1  = (const float*)d_in[17];
    const float* ff_b1  = (const float*)d_in[18];
    const float* ff_w2  = (const float*)d_in[19];
    const float* ff_b2  = (const float*)d_in[20];
    float* out = (float*)d_out;

    k_qkv_gate<<<79, 256>>>(x, ln1_g, ln1_b, w_qkv,
                            x_pe, tokens, conv_k, bn_g, bn_b, bn_rm, bn_rv, fc_w1, fc_w2);
    k_attn<<<dim3(13, NH), 160>>>();
    k_oproj<<<13, 256>>>(w_out, b_out, x);
    k_ff1<<<dim3(13, 4), 256>>>(ln2_g, ln2_b, ff_w1, ff_b1);
    k_ff2<<<13, 256>>>(ff_w2, ff_b2, out);
}

// round 4
// speedup vs baseline: 2.0097x; 2.0097x over previous
#include <cuda_runtime.h>
#include <math.h>

#define DD 196
#define SEQ 65
#define NCH 64
#define NH 8
#define DH 64
#define INNER 512
#define MLP 784

// Scratch (allocation-free, __device__ globals)
__device__ float g_xatt[SEQ * DD];
__device__ float g_qkv[SEQ * 3 * INNER];
__device__ float g_o[SEQ * INNER];
__device__ float g_x2[SEQ * DD];
__device__ float g_ff[SEQ * MLP];

// ---------------------------------------------------------------------------
// Gate path (device function, run by one block)
// ---------------------------------------------------------------------------
__device__ void gate_block(const float* __restrict__ x_pe, const float* __restrict__ tokens,
                           const float* __restrict__ conv_k,
                           const float* __restrict__ bn_g, const float* __restrict__ bn_b,
                           const float* __restrict__ bn_rm, const float* __restrict__ bn_rv,
                           const float* __restrict__ fc_w1, const float* __restrict__ fc_w2) {
    __shared__ float b1s[NCH];
    __shared__ float b2s[NCH];
    __shared__ float csm[NCH];
    __shared__ float hid[12];

    int t = threadIdx.x;
    int w = t >> 5, l = t & 31;

    float km0 = conv_k[3], km1 = conv_k[4], km2 = conv_k[5];
    float s = bn_g[0] * rsqrtf(bn_rv[0] + 1e-5f);
    float bias = bn_b[0] - bn_rm[0] * s;

    for (int ch = w; ch < NCH; ch += 8) {
        const float* row = x_pe + ch * DD;
        float sum = 0.f;
        for (int i = l; i < DD; i += 32) {
            float left  = (i > 0)      ? row[i - 1] : 0.f;
            float mid   = row[i];
            float right = (i < DD - 1) ? row[i + 1] : 0.f;
            float conv = km0 * left + km1 * mid + km2 * right;
            float a = fmaxf(conv * s + bias, 0.f);
            g_xatt[ch * DD + i] = a;
            sum += a;
        }
        #pragma unroll
        for (int o = 16; o; o >>= 1) sum += __shfl_xor_sync(0xffffffffu, sum, o);
        if (l == 0) b1s[ch] = sum * (1.f / DD);
    }
    __syncthreads();

    if (t < NCH) {
        float v = b1s[t];
        int rank = 0, cnt = 0;
        float mx = -1e30f, mn = 1e30f;
        for (int j = 0; j < NCH; j++) {
            float u = b1s[j];
            rank += (u < v) || (u == v && j < t);
            cnt += (u <= 0.f);
            mx = fmaxf(mx, u);
            mn = fminf(mn, u);
        }
        int middle = (cnt == NCH) ? 0 : cnt;
        if (mx < 0.f || mn > 0.f) middle = 32;
        float ls = (float)middle, le = (float)(NCH - middle);
        float o;
        if (rank < middle) o = v - 1.f / (1.f + powf(ls, v));
        else               o = v + 1.f / (1.f + powf(le, -v));
        b2s[t] = o;
    }
    __syncthreads();

    if (t < 12) {
        float acc = 0.f;
        for (int c = 0; c < NCH; c++) acc += b2s[c] * fc_w1[c * 12 + t];
        hid[t] = fmaxf(acc, 0.f);
    }
    __syncthreads();

    if (t < NCH) {
        float acc = 0.f;
        #pragma unroll
        for (int k = 0; k < 12; k++) acc += hid[k] * fc_w2[k * NCH + t];
        csm[t] = 1.f / (1.f + expf(-acc));
    }
    __syncthreads();

    for (int i = t; i < NCH * DD; i += 256) g_xatt[i] *= csm[i / DD];
    for (int i = t; i < DD; i += 256) g_xatt[NCH * DD + i] = tokens[i];
}

// ---------------------------------------------------------------------------
// In-block LayerNorm over a 5-row tile held in smem. 256 threads.
// ---------------------------------------------------------------------------
__device__ __forceinline__ void ln_tile(const float* __restrict__ xs,
                                        float* __restrict__ hs,
                                        const float* __restrict__ g,
                                        const float* __restrict__ b,
                                        float* __restrict__ smean,
                                        float* __restrict__ sinv) {
    int t = threadIdx.x, w = t >> 5, l = t & 31;
    if (w < 5) {
        float sum = 0.f, sq = 0.f;
        for (int i = l; i < DD; i += 32) {
            float v = xs[w * DD + i];
            sum += v; sq += v * v;
        }
        #pragma unroll
        for (int o = 16; o; o >>= 1) {
            sum += __shfl_xor_sync(0xffffffffu, sum, o);
            sq  += __shfl_xor_sync(0xffffffffu, sq, o);
        }
        if (l == 0) {
            float mean = sum * (1.f / DD);
            float var = sq * (1.f / DD) - mean * mean;
            smean[w] = mean;
            sinv[w] = rsqrtf(var + 1e-5f);
        }
    }
    __syncthreads();
    for (int i = t; i < 5 * DD; i += 256) {
        int r = i / DD, c = i - r * DD;
        hs[i] = (xs[i] - smean[r]) * sinv[r] * g[c] + b[c];
    }
    __syncthreads();
}

// ---------------------------------------------------------------------------
// Fused: blocks 0..77 do LN1 + QKV GEMM; block 78 does the gate path.
// Manual double-buffered weight pipeline: KS=28, 7 groups over K=196.
// ---------------------------------------------------------------------------
__global__ void __launch_bounds__(256, 1) k_qkv_gate(
        const float* __restrict__ x, const float* __restrict__ ln_g,
        const float* __restrict__ ln_b, const float* __restrict__ w,
        const float* __restrict__ x_pe, const float* __restrict__ tokens,
        const float* __restrict__ conv_k,
        const float* __restrict__ bn_g, const float* __restrict__ bn_b,
        const float* __restrict__ bn_rm, const float* __restrict__ bn_rv,
        const float* __restrict__ fc_w1, const float* __restrict__ fc_w2) {
    if (blockIdx.x == 78) {
        gate_block(x_pe, tokens, conv_k, bn_g, bn_b, bn_rm, bn_rv, fc_w1, fc_w2);
        return;
    }
    __shared__ float xs[5 * DD];
    __shared__ float hs[5 * DD];
    __shared__ float smean[5], sinv[5];
    int bx = blockIdx.x / 6, by = blockIdx.x % 6;
    int r0 = bx * 5;
    int col = by * 256 + threadIdx.x;
    for (int i = threadIdx.x; i < 5 * DD; i += 256) xs[i] = x[r0 * DD + i];
    __syncthreads();
    ln_tile(xs, hs, ln_g, ln_b, smean, sinv);

    const int KS = 28;  // 196 = 28 * 7
    float acc[5] = {0.f, 0.f, 0.f, 0.f, 0.f};
    float wv[KS];
    #pragma unroll
    for (int u = 0; u < KS; u++) wv[u] = w[u * 1536 + col];
    for (int k0 = 0; k0 < DD - KS; k0 += KS) {
        float nv[KS];
        #pragma unroll
        for (int u = 0; u < KS; u++) nv[u] = w[(k0 + KS + u) * 1536 + col];
        #pragma unroll
        for (int u = 0; u < KS; u++) {
            float wvv = wv[u];
            #pragma unroll
            for (int r = 0; r < 5; r++) acc[r] += hs[r * DD + k0 + u] * wvv;
        }
        #pragma unroll
        for (int u = 0; u < KS; u++) wv[u] = nv[u];
    }
    #pragma unroll
    for (int u = 0; u < KS; u++) {
        float wvv = wv[u];
        #pragma unroll
        for (int r = 0; r < 5; r++) acc[r] += hs[r * DD + (DD - KS) + u] * wvv;
    }
    #pragma unroll
    for (int r = 0; r < 5; r++) g_qkv[(r0 + r) * 1536 + col] = acc[r];
}

// ---------------------------------------------------------------------------
// Attention: grid (13 row-tiles, 8 heads), 160 threads.
// ---------------------------------------------------------------------------
__global__ void k_attn() {
    __shared__ float skT[DH * 67];
    __shared__ float sv[SEQ * DH];
    __shared__ float sq[5 * DH];
    __shared__ float sp[5 * 66];
    int h = blockIdx.y, r0 = blockIdx.x * 5;
    int t = threadIdx.x;

    for (int i = t; i < SEQ * DH; i += 160) {
        int j = i >> 6, d = i & 63;
        skT[d * 67 + j] = g_qkv[j * 1536 + INNER + h * 64 + d];
        sv[i]           = g_qkv[j * 1536 + 2 * INNER + h * 64 + d];
    }
    for (int i = t; i < 5 * DH; i += 160) {
        int r = i >> 6, d = i & 63;
        sq[i] = g_qkv[(r0 + r) * 1536 + h * 64 + d];
    }
    __syncthreads();

    for (int e = t; e < 5 * SEQ; e += 160) {
        int i = e / SEQ, j = e - i * SEQ;
        float acc = 0.f;
        #pragma unroll
        for (int d = 0; d < DH; d++) acc += sq[i * 64 + d] * skT[d * 67 + j];
        sp[i * 66 + j] = acc * 0.125f;
    }
    __syncthreads();

    int w = t >> 5, l = t & 31;
    if (w < 5) {
        float mx = -1e30f;
        for (int j = l; j < SEQ; j += 32) mx = fmaxf(mx, sp[w * 66 + j]);
        #pragma unroll
        for (int o = 16; o; o >>= 1) mx = fmaxf(mx, __shfl_xor_sync(0xffffffffu, mx, o));
        float sum = 0.f;
        for (int j = l; j < SEQ; j += 32) {
            float p = expf(sp[w * 66 + j] - mx);
            sp[w * 66 + j] = p;
            sum += p;
        }
        #pragma unroll
        for (int o = 16; o; o >>= 1) sum += __shfl_xor_sync(0xffffffffu, sum, o);
        float inv = 1.f / sum;
        for (int j = l; j < SEQ; j += 32) sp[w * 66 + j] *= inv;
    }
    __syncthreads();

    for (int e = t; e < 5 * DH; e += 160) {
        int i = e >> 6, d = e & 63;
        float acc = 0.f;
        #pragma unroll 5
        for (int j = 0; j < SEQ; j++) acc += sp[i * 66 + j] * sv[j * 64 + d];
        g_o[(r0 + i) * INNER + h * 64 + d] = acc;
    }
}

// ---------------------------------------------------------------------------
// Out-proj + residuals. KS=32, 16 groups over K=512.
// ---------------------------------------------------------------------------
__global__ void __launch_bounds__(256, 1) k_oproj(const float* __restrict__ w_out,
                                                  const float* __restrict__ b_out,
                                                  const float* __restrict__ x) {
    __shared__ float so[5 * INNER];
    int r0 = blockIdx.x * 5;
    for (int i = threadIdx.x; i < 5 * INNER; i += 256) so[i] = g_o[r0 * INNER + i];
    __syncthreads();
    int col = threadIdx.x;
    if (col < DD) {
        const int KS = 32;  // 512 = 32 * 16
        float acc[5] = {0.f, 0.f, 0.f, 0.f, 0.f};
        float wv[KS];
        #pragma unroll
        for (int u = 0; u < KS; u++) wv[u] = w_out[u * DD + col];
        for (int k0 = 0; k0 < INNER - KS; k0 += KS) {
            float nv[KS];
            #pragma unroll
            for (int u = 0; u < KS; u++) nv[u] = w_out[(k0 + KS + u) * DD + col];
            #pragma unroll
            for (int u = 0; u < KS; u++) {
                float wvv = wv[u];
                #pragma unroll
                for (int r = 0; r < 5; r++) acc[r] += so[r * INNER + k0 + u] * wvv;
            }
            #pragma unroll
            for (int u = 0; u < KS; u++) wv[u] = nv[u];
        }
        #pragma unroll
        for (int u = 0; u < KS; u++) {
            float wvv = wv[u];
            #pragma unroll
            for (int r = 0; r < 5; r++) acc[r] += so[r * INNER + (INNER - KS) + u] * wvv;
        }
        float bb = b_out[col];
        #pragma unroll
        for (int r = 0; r < 5; r++) {
            int row = r0 + r;
            g_x2[row * DD + col] = acc[r] + bb + x[row * DD + col] + g_xatt[row * DD + col];
        }
    }
}

// ---------------------------------------------------------------------------
// LN2 + FF1 + exact GELU. KS=28, 7 groups over K=196.
// ---------------------------------------------------------------------------
__global__ void __launch_bounds__(256, 1) k_ff1(const float* __restrict__ ln_g,
                                                const float* __restrict__ ln_b,
                                                const float* __restrict__ w1,
                                                const float* __restrict__ b1v) {
    __shared__ float xs[5 * DD];
    __shared__ float hs[5 * DD];
    __shared__ float smean[5], sinv[5];
    int r0 = blockIdx.x * 5;
    int col = blockIdx.y * 256 + threadIdx.x;
    for (int i = threadIdx.x; i < 5 * DD; i += 256) xs[i] = g_x2[r0 * DD + i];
    __syncthreads();
    ln_tile(xs, hs, ln_g, ln_b, smean, sinv);
    if (col < MLP) {
        const int KS = 28;
        float acc[5] = {0.f, 0.f, 0.f, 0.f, 0.f};
        float wv[KS];
        #pragma unroll
        for (int u = 0; u < KS; u++) wv[u] = w1[u * MLP + col];
        for (int k0 = 0; k0 < DD - KS; k0 += KS) {
            float nv[KS];
            #pragma unroll
            for (int u = 0; u < KS; u++) nv[u] = w1[(k0 + KS + u) * MLP + col];
            #pragma unroll
            for (int u = 0; u < KS; u++) {
                float wvv = wv[u];
                #pragma unroll
                for (int r = 0; r < 5; r++) acc[r] += hs[r * DD + k0 + u] * wvv;
            }
            #pragma unroll
            for (int u = 0; u < KS; u++) wv[u] = nv[u];
        }
        #pragma unroll
        for (int u = 0; u < KS; u++) {
            float wvv = wv[u];
            #pragma unroll
            for (int r = 0; r < 5; r++) acc[r] += hs[r * DD + (DD - KS) + u] * wvv;
        }
        float bb = b1v[col];
        #pragma unroll
        for (int r = 0; r < 5; r++) {
            float v = acc[r] + bb;
            g_ff[(r0 + r) * MLP + col] = 0.5f * v * (1.f + erff(v * 0.70710678118654752f));
        }
    }
}

// ---------------------------------------------------------------------------
// FF2 + residual. KS=28, 28 groups over K=784.
// ---------------------------------------------------------------------------
__global__ void __launch_bounds__(256, 1) k_ff2(const float* __restrict__ w2,
                                                const float* __restrict__ b2v,
                                                float* __restrict__ out) {
    __shared__ float sg[5 * MLP];
    int r0 = blockIdx.x * 5;
    for (int i = threadIdx.x; i < 5 * MLP; i += 256) sg[i] = g_ff[r0 * MLP + i];
    __syncthreads();
    int col = threadIdx.x;
    if (col < DD) {
        const int KS = 28;  // 784 = 28 * 28
        float acc[5] = {0.f, 0.f, 0.f, 0.f, 0.f};
        float wv[KS];
        #pragma unroll
        for (int u = 0; u < KS; u++) wv[u] = w2[u * DD + col];
        for (int k0 = 0; k0 < MLP - KS; k0 += KS) {
            float nv[KS];
            #pragma unroll
            for (int u = 0; u < KS; u++) nv[u] = w2[(k0 + KS + u) * DD + col];
            #pragma unroll
            for (int u = 0; u < KS; u++) {
                float wvv = wv[u];
                #pragma unroll
                for (int r = 0; r < 5; r++) acc[r] += sg[r * MLP + k0 + u] * wvv;
            }
            #pragma unroll
            for (int u = 0; u < KS; u++) wv[u] = nv[u];
        }
        #pragma unroll
        for (int u = 0; u < KS; u++) {
            float wvv = wv[u];
            #pragma unroll
            for (int r = 0; r < 5; r++) acc[r] += sg[r * MLP + (MLP - KS) + u] * wvv;
        }
        float bb = b2v[col];
        #pragma unroll
        for (int r = 0; r < 5; r++) {
            int row = r0 + r;
            out[row * DD + col] = acc[r] + bb + g_x2[row * DD + col];
        }
    }
}

// ---------------------------------------------------------------------------
extern "C" void kernel_launch(void* const* d_in, const int* in_sizes, int n_in,
                              void* d_out, int out_size) {
    const float* x      = (const float*)d_in[0];
    const float* tokens = (const float*)d_in[1];
    const float* x_pe   = (const float*)d_in[2];
    const float* conv_k = (const float*)d_in[3];
    const float* bn_g   = (const float*)d_in[4];
    const float* bn_b   = (const float*)d_in[5];
    const float* bn_rm  = (const float*)d_in[6];
    const float* bn_rv  = (const float*)d_in[7];
    const float* fc_w1  = (const float*)d_in[8];
    const float* fc_w2  = (const float*)d_in[9];
    const float* ln1_g  = (const float*)d_in[10];
    const float* ln1_b  = (const float*)d_in[11];
    const float* ln2_g  = (const float*)d_in[12];
    const float* ln2_b  = (const float*)d_in[13];
    const float* w_qkv  = (const float*)d_in[14];
    const float* w_out  = (const float*)d_in[15];
    const float* b_out  = (const float*)d_in[16];
    const float* ff_w1  = (const float*)d_in[17];
    const float* ff_b1  = (const float*)d_in[18];
    const float* ff_w2  = (const float*)d_in[19];
    const float* ff_b2  = (const float*)d_in[20];
    float* out = (float*)d_out;

    k_qkv_gate<<<79, 256>>>(x, ln1_g, ln1_b, w_qkv,
                            x_pe, tokens, conv_k, bn_g, bn_b, bn_rm, bn_rv, fc_w1, fc_w2);
    k_attn<<<dim3(13, NH), 160>>>();
    k_oproj<<<13, 256>>>(w_out, b_out, x);
    k_ff1<<<dim3(13, 4), 256>>>(ln2_g, ln2_b, ff_w1, ff_b1);
    k_ff2<<<13, 256>>>(ff_w2, ff_b2, out);
}

// round 5
// speedup vs baseline: 2.9085x; 1.4472x over previous
#include <cuda_runtime.h>
#include <math.h>

#define DD 196
#define SEQ 65
#define NCH 64
#define NH 8
#define DH 64
#define INNER 512
#define MLP 784
#define NBLK 105

// Scratch (allocation-free, __device__ globals)
__device__ float g_xatt[SEQ * DD];
__device__ float g_qkv[SEQ * 3 * INNER];
__device__ float g_x2[SEQ * DD];
__device__ float g_partC[8 * SEQ * DD];   // attn+oproj partials (per head)
__device__ float g_partE[8 * SEQ * DD];   // ff2 partials (per MLP chunk)

// Grid-wide barrier (generation counter; all NBLK blocks co-resident)
__device__ unsigned g_gen = 0;
__device__ unsigned g_cnt = 0;

__device__ __forceinline__ void gsync() {
    __syncthreads();
    if (threadIdx.x == 0) {
        unsigned gen = *(volatile unsigned*)&g_gen;
        __threadfence();
        unsigned prev = atomicAdd(&g_cnt, 1u);
        if (prev == NBLK - 1) {
            g_cnt = 0;
            __threadfence();
            atomicAdd(&g_gen, 1u);
        } else {
            while (*(volatile unsigned*)&g_gen == gen) { __nanosleep(64); }
        }
        __threadfence();
    }
    __syncthreads();
}

// Double-buffered 5-row GEMM inner loop. K = KS*NG.
// acts in smem: acts[r*astride + k]; weights: wbase[k*wstride]
template <int KS, int NG>
__device__ __forceinline__ void gemm5(const float* __restrict__ wbase, int wstride,
                                      const float* __restrict__ acts, int astride,
                                      float* acc) {
    float wv[KS];
    #pragma unroll
    for (int u = 0; u < KS; u++) wv[u] = wbase[u * wstride];
    #pragma unroll 1
    for (int g = 0; g < NG - 1; g++) {
        int k0 = g * KS;
        float nv[KS];
        #pragma unroll
        for (int u = 0; u < KS; u++) nv[u] = wbase[(k0 + KS + u) * wstride];
        #pragma unroll
        for (int u = 0; u < KS; u++) {
            float wvv = wv[u];
            #pragma unroll
            for (int r = 0; r < 5; r++) acc[r] += acts[r * astride + k0 + u] * wvv;
        }
        #pragma unroll
        for (int u = 0; u < KS; u++) wv[u] = nv[u];
    }
    const int kl = (NG - 1) * KS;
    #pragma unroll
    for (int u = 0; u < KS; u++) {
        float wvv = wv[u];
        #pragma unroll
        for (int r = 0; r < 5; r++) acc[r] += acts[r * astride + kl + u] * wvv;
    }
}

// In-block LayerNorm over a 5-row tile held in smem. 256 threads.
__device__ __forceinline__ void ln_tile(const float* __restrict__ xs,
                                        float* __restrict__ hs,
                                        const float* __restrict__ g,
                                        const float* __restrict__ b,
                                        float* __restrict__ smean,
                                        float* __restrict__ sinv) {
    int t = threadIdx.x, w = t >> 5, l = t & 31;
    if (w < 5) {
        float sum = 0.f, sq = 0.f;
        for (int i = l; i < DD; i += 32) {
            float v = xs[w * DD + i];
            sum += v; sq += v * v;
        }
        #pragma unroll
        for (int o = 16; o; o >>= 1) {
            sum += __shfl_xor_sync(0xffffffffu, sum, o);
            sq  += __shfl_xor_sync(0xffffffffu, sq, o);
        }
        if (l == 0) {
            float mean = sum * (1.f / DD);
            float var = sq * (1.f / DD) - mean * mean;
            smean[w] = mean;
            sinv[w] = rsqrtf(var + 1e-5f);
        }
    }
    __syncthreads();
    for (int i = t; i < 5 * DD; i += 256) {
        int r = i / DD, c = i - r * DD;
        hs[i] = (xs[i] - smean[r]) * sinv[r] * g[c] + b[c];
    }
    __syncthreads();
}

// Gate path (one block)
__device__ void gate_block(float* __restrict__ sm,
                           const float* __restrict__ x_pe, const float* __restrict__ tokens,
                           const float* __restrict__ conv_k,
                           const float* __restrict__ bn_g, const float* __restrict__ bn_b,
                           const float* __restrict__ bn_rm, const float* __restrict__ bn_rv,
                           const float* __restrict__ fc_w1, const float* __restrict__ fc_w2) {
    float* b1s = sm;
    float* b2s = sm + 64;
    float* csm = sm + 128;
    float* hid = sm + 192;

    int t = threadIdx.x;
    int w = t >> 5, l = t & 31;

    float km0 = conv_k[3], km1 = conv_k[4], km2 = conv_k[5];
    float s = bn_g[0] * rsqrtf(bn_rv[0] + 1e-5f);
    float bias = bn_b[0] - bn_rm[0] * s;

    for (int ch = w; ch < NCH; ch += 8) {
        const float* row = x_pe + ch * DD;
        float sum = 0.f;
        for (int i = l; i < DD; i += 32) {
            float left  = (i > 0)      ? row[i - 1] : 0.f;
            float mid   = row[i];
            float right = (i < DD - 1) ? row[i + 1] : 0.f;
            float conv = km0 * left + km1 * mid + km2 * right;
            float a = fmaxf(conv * s + bias, 0.f);
            g_xatt[ch * DD + i] = a;
            sum += a;
        }
        #pragma unroll
        for (int o = 16; o; o >>= 1) sum += __shfl_xor_sync(0xffffffffu, sum, o);
        if (l == 0) b1s[ch] = sum * (1.f / DD);
    }
    __syncthreads();

    if (t < NCH) {
        float v = b1s[t];
        int rank = 0, cnt = 0;
        float mx = -1e30f, mn = 1e30f;
        for (int j = 0; j < NCH; j++) {
            float u = b1s[j];
            rank += (u < v) || (u == v && j < t);
            cnt += (u <= 0.f);
            mx = fmaxf(mx, u);
            mn = fminf(mn, u);
        }
        int middle = (cnt == NCH) ? 0 : cnt;
        if (mx < 0.f || mn > 0.f) middle = 32;
        float ls = (float)middle, le = (float)(NCH - middle);
        float o;
        if (rank < middle) o = v - 1.f / (1.f + powf(ls, v));
        else               o = v + 1.f / (1.f + powf(le, -v));
        b2s[t] = o;
    }
    __syncthreads();

    if (t < 12) {
        float acc = 0.f;
        for (int c = 0; c < NCH; c++) acc += b2s[c] * fc_w1[c * 12 + t];
        hid[t] = fmaxf(acc, 0.f);
    }
    __syncthreads();

    if (t < NCH) {
        float acc = 0.f;
        #pragma unroll
        for (int k = 0; k < 12; k++) acc += hid[k] * fc_w2[k * NCH + t];
        csm[t] = 1.f / (1.f + expf(-acc));
    }
    __syncthreads();

    for (int i = t; i < NCH * DD; i += 256) g_xatt[i] *= csm[i / DD];
    for (int i = t; i < DD; i += 256) g_xatt[NCH * DD + i] = tokens[i];
}

// ---------------------------------------------------------------------------
// The single persistent kernel.
// ---------------------------------------------------------------------------
__global__ void __launch_bounds__(256, 1) k_all(
        const float* __restrict__ x, const float* __restrict__ tokens,
        const float* __restrict__ x_pe, const float* __restrict__ conv_k,
        const float* __restrict__ bn_g, const float* __restrict__ bn_b,
        const float* __restrict__ bn_rm, const float* __restrict__ bn_rv,
        const float* __restrict__ fc_w1, const float* __restrict__ fc_w2,
        const float* __restrict__ ln1_g, const float* __restrict__ ln1_b,
        const float* __restrict__ ln2_g, const float* __restrict__ ln2_b,
        const float* __restrict__ w_qkv, const float* __restrict__ w_out,
        const float* __restrict__ b_out,
        const float* __restrict__ ff_w1, const float* __restrict__ ff_b1,
        const float* __restrict__ ff_w2, const float* __restrict__ ff_b2,
        float* __restrict__ out) {
    __shared__ float sm[9420];
    int b = blockIdx.x;
    int t = threadIdx.x;

    // ===== Phase A: LN1 + QKV (blocks 0..103, 13 tiles x 8 col-chunks of 192)
    //                gate path on block 104 =====
    if (b == 104) {
        gate_block(sm, x_pe, tokens, conv_k, bn_g, bn_b, bn_rm, bn_rv, fc_w1, fc_w2);
    } else {
        float* xs = sm;
        float* hs = sm + 980;
        float* smean = sm + 1960;
        float* sinv = sm + 1966;
        int tile = b >> 3, chunk = b & 7;
        int r0 = tile * 5;
        for (int i = t; i < 5 * DD; i += 256) xs[i] = x[r0 * DD + i];
        __syncthreads();
        ln_tile(xs, hs, ln1_g, ln1_b, smean, sinv);
        if (t < 192) {
            int col = chunk * 192 + t;
            float acc[5] = {0.f, 0.f, 0.f, 0.f, 0.f};
            gemm5<28, 7>(w_qkv + col, 1536, hs, DD, acc);
            #pragma unroll
            for (int r = 0; r < 5; r++) g_qkv[(r0 + r) * 1536 + col] = acc[r];
        }
    }
    gsync();

    // ===== Phase B: attention + out-proj partial (blocks 0..103: 13 tiles x 8 heads) =====
    if (b < 104) {
        float* skT = sm;             // 64 x 67
        float* sv  = sm + 4288;      // 65 x 64
        float* sq  = sm + 8448;      // 5 x 64
        float* sp  = sm + 8768;      // 5 x 66
        float* so2 = sm + 9098;      // 5 x 64
        int tile = b >> 3, h = b & 7;
        int r0 = tile * 5;

        for (int i = t; i < SEQ * DH; i += 256) {
            int j = i >> 6, d = i & 63;
            skT[d * 67 + j] = g_qkv[j * 1536 + INNER + h * 64 + d];
            sv[i]           = g_qkv[j * 1536 + 2 * INNER + h * 64 + d];
        }
        for (int i = t; i < 5 * DH; i += 256) {
            int r = i >> 6, d = i & 63;
            sq[i] = g_qkv[(r0 + r) * 1536 + h * 64 + d];
        }
        __syncthreads();

        for (int e = t; e < 5 * SEQ; e += 256) {
            int i = e / SEQ, j = e - i * SEQ;
            float acc = 0.f;
            #pragma unroll
            for (int d = 0; d < DH; d++) acc += sq[i * 64 + d] * skT[d * 67 + j];
            sp[i * 66 + j] = acc * 0.125f;
        }
        __syncthreads();

        int w = t >> 5, l = t & 31;
        if (w < 5) {
            float mx = -1e30f;
            for (int j = l; j < SEQ; j += 32) mx = fmaxf(mx, sp[w * 66 + j]);
            #pragma unroll
            for (int o = 16; o; o >>= 1) mx = fmaxf(mx, __shfl_xor_sync(0xffffffffu, mx, o));
            float sum = 0.f;
            for (int j = l; j < SEQ; j += 32) {
                float p = expf(sp[w * 66 + j] - mx);
                sp[w * 66 + j] = p;
                sum += p;
            }
            #pragma unroll
            for (int o = 16; o; o >>= 1) sum += __shfl_xor_sync(0xffffffffu, sum, o);
            float inv = 1.f / sum;
            for (int j = l; j < SEQ; j += 32) sp[w * 66 + j] *= inv;
        }
        __syncthreads();

        for (int e = t; e < 5 * DH; e += 256) {
            int i = e >> 6, d = e & 63;
            float acc = 0.f;
            #pragma unroll 5
            for (int j = 0; j < SEQ; j++) acc += sp[i * 66 + j] * sv[j * 64 + d];
            so2[e] = acc;
        }
        __syncthreads();

        // out-proj partial for this head's K-slice: K = 64
        if (t < DD) {
            float acc[5] = {0.f, 0.f, 0.f, 0.f, 0.f};
            gemm5<16, 4>(w_out + (h * 64) * DD + t, DD, so2, 64, acc);
            #pragma unroll
            for (int r = 0; r < 5; r++)
                g_partC[(h * SEQ + r0 + r) * DD + t] = acc[r];
        }
    }
    gsync();

    // ===== Phase C: reduce 8 partials + b_out + x + x_att -> g_x2 =====
    for (int i = b * 256 + t; i < SEQ * DD; i += NBLK * 256) {
        int col = i % DD;
        float acc = x[i] + g_xatt[i] + b_out[col];
        #pragma unroll
        for (int ks = 0; ks < 8; ks++) acc += g_partC[ks * SEQ * DD + i];
        g_x2[i] = acc;
    }
    gsync();

    // ===== Phase D: LN2 + FF1 + GELU + FF2-partial (13 tiles x 8 chunks of 98) =====
    if (b < 104) {
        float* xs = sm;
        float* hs = sm + 980;
        float* smean = sm + 1960;
        float* sinv = sm + 1966;
        float* sg = sm + 1972;       // 5 x 98
        int tile = b >> 3, chunk = b & 7;
        int r0 = tile * 5;
        for (int i = t; i < 5 * DD; i += 256) xs[i] = g_x2[r0 * DD + i];
        __syncthreads();
        ln_tile(xs, hs, ln2_g, ln2_b, smean, sinv);
        if (t < 98) {
            int col = chunk * 98 + t;
            float acc[5] = {0.f, 0.f, 0.f, 0.f, 0.f};
            gemm5<28, 7>(ff_w1 + col, MLP, hs, DD, acc);
            float bb = ff_b1[col];
            #pragma unroll
            for (int r = 0; r < 5; r++) {
                float v = acc[r] + bb;
                sg[r * 98 + t] = 0.5f * v * (1.f + erff(v * 0.70710678118654752f));
            }
        }
        __syncthreads();
        // ff2 partial: K = 98 slice of MLP
        if (t < DD) {
            float acc[5] = {0.f, 0.f, 0.f, 0.f, 0.f};
            gemm5<14, 7>(ff_w2 + (chunk * 98) * DD + t, DD, sg, 98, acc);
            #pragma unroll
            for (int r = 0; r < 5; r++)
                g_partE[(chunk * SEQ + r0 + r) * DD + t] = acc[r];
        }
    }
    gsync();

    // ===== Phase E: reduce 8 partials + b2 + g_x2 -> out =====
    for (int i = b * 256 + t; i < SEQ * DD; i += NBLK * 256) {
        int col = i % DD;
        float acc = g_x2[i] + ff_b2[col];
        #pragma unroll
        for (int ks = 0; ks < 8; ks++) acc += g_partE[ks * SEQ * DD + i];
        out[i] = acc;
    }
}

// ---------------------------------------------------------------------------
extern "C" void kernel_launch(void* const* d_in, const int* in_sizes, int n_in,
                              void* d_out, int out_size) {
    const float* x      = (const float*)d_in[0];
    const float* tokens = (const float*)d_in[1];
    const float* x_pe   = (const float*)d_in[2];
    const float* conv_k = (const float*)d_in[3];
    const float* bn_g   = (const float*)d_in[4];
    const float* bn_b   = (const float*)d_in[5];
    const float* bn_rm  = (const float*)d_in[6];
    const float* bn_rv  = (const float*)d_in[7];
    const float* fc_w1  = (const float*)d_in[8];
    const float* fc_w2  = (const float*)d_in[9];
    const float* ln1_g  = (const float*)d_in[10];
    const float* ln1_b  = (const float*)d_in[11];
    const float* ln2_g  = (const float*)d_in[12];
    const float* ln2_b  = (const float*)d_in[13];
    const float* w_qkv  = (const float*)d_in[14];
    const float* w_out  = (const float*)d_in[15];
    const float* b_out  = (const float*)d_in[16];
    const float* ff_w1  = (const float*)d_in[17];
    const float* ff_b1  = (const float*)d_in[18];
    const float* ff_w2  = (const float*)d_in[19];
    const float* ff_b2  = (const float*)d_in[20];
    float* out = (float*)d_out;

    k_all<<<NBLK, 256>>>(x, tokens, x_pe, conv_k, bn_g, bn_b, bn_rm, bn_rv,
                         fc_w1, fc_w2, ln1_g, ln1_b, ln2_g, ln2_b,
                         w_qkv, w_out, b_out, ff_w1, ff_b1, ff_w2, ff_b2, out);
}

// round 6
// speedup vs baseline: 3.9752x; 1.3668x over previous
#include <cuda_runtime.h>
#include <math.h>

#define DD 196
#define SEQ 65
#define NCH 64
#define NH 8
#define DH 64
#define INNER 512
#define MLP 784
#define NBLK 105
#define NT 512

// Scratch (allocation-free, __device__ globals)
__device__ float g_xatt[SEQ * DD];
__device__ float g_qkv[SEQ * 3 * INNER];
__device__ float g_x2[SEQ * DD];
__device__ float g_partC[8 * SEQ * DD];   // attn+oproj partials (per head)
__device__ float g_partE[8 * SEQ * DD];   // ff2 partials (per MLP chunk)

// Grid-wide barrier (generation counter; all NBLK blocks co-resident)
__device__ unsigned g_gen = 0;
__device__ unsigned g_cnt = 0;

__device__ __forceinline__ void gsync() {
    __syncthreads();
    if (threadIdx.x == 0) {
        unsigned gen = *(volatile unsigned*)&g_gen;
        __threadfence();
        unsigned prev = atomicAdd(&g_cnt, 1u);
        if (prev == NBLK - 1) {
            g_cnt = 0;
            __threadfence();
            atomicAdd(&g_gen, 1u);
        } else {
            while (*(volatile unsigned*)&g_gen == gen) { __nanosleep(64); }
        }
        __threadfence();
    }
    __syncthreads();
}

// Double-buffered 5-row GEMM inner loop over K = KS*NG.
template <int KS, int NG>
__device__ __forceinline__ void gemm5(const float* __restrict__ wbase, int wstride,
                                      const float* __restrict__ acts, int astride,
                                      float* acc) {
    float wv[KS];
    #pragma unroll
    for (int u = 0; u < KS; u++) wv[u] = wbase[u * wstride];
    #pragma unroll 1
    for (int g = 0; g < NG - 1; g++) {
        int k0 = g * KS;
        float nv[KS];
        #pragma unroll
        for (int u = 0; u < KS; u++) nv[u] = wbase[(k0 + KS + u) * wstride];
        #pragma unroll
        for (int u = 0; u < KS; u++) {
            float wvv = wv[u];
            #pragma unroll
            for (int r = 0; r < 5; r++) acc[r] += acts[r * astride + k0 + u] * wvv;
        }
        #pragma unroll
        for (int u = 0; u < KS; u++) wv[u] = nv[u];
    }
    const int kl = (NG - 1) * KS;
    #pragma unroll
    for (int u = 0; u < KS; u++) {
        float wvv = wv[u];
        #pragma unroll
        for (int r = 0; r < 5; r++) acc[r] += acts[r * astride + kl + u] * wvv;
    }
}

// In-block LayerNorm over a 5-row tile held in smem. NT threads.
__device__ __forceinline__ void ln_tile(const float* __restrict__ xs,
                                        float* __restrict__ hs,
                                        const float* __restrict__ g,
                                        const float* __restrict__ b,
                                        float* __restrict__ smean,
                                        float* __restrict__ sinv) {
    int t = threadIdx.x, w = t >> 5, l = t & 31;
    if (w < 5) {
        float sum = 0.f, sq = 0.f;
        for (int i = l; i < DD; i += 32) {
            float v = xs[w * DD + i];
            sum += v; sq += v * v;
        }
        #pragma unroll
        for (int o = 16; o; o >>= 1) {
            sum += __shfl_xor_sync(0xffffffffu, sum, o);
            sq  += __shfl_xor_sync(0xffffffffu, sq, o);
        }
        if (l == 0) {
            float mean = sum * (1.f / DD);
            float var = sq * (1.f / DD) - mean * mean;
            smean[w] = mean;
            sinv[w] = rsqrtf(var + 1e-5f);
        }
    }
    __syncthreads();
    for (int i = t; i < 5 * DD; i += NT) {
        int r = i / DD, c = i - r * DD;
        hs[i] = (xs[i] - smean[r]) * sinv[r] * g[c] + b[c];
    }
    __syncthreads();
}

// Gate path (one block)
__device__ void gate_block(float* __restrict__ sm,
                           const float* __restrict__ x_pe, const float* __restrict__ tokens,
                           const float* __restrict__ conv_k,
                           const float* __restrict__ bn_g, const float* __restrict__ bn_b,
                           const float* __restrict__ bn_rm, const float* __restrict__ bn_rv,
                           const float* __restrict__ fc_w1, const float* __restrict__ fc_w2) {
    float* b1s = sm;
    float* b2s = sm + 64;
    float* csm = sm + 128;
    float* hid = sm + 192;

    int t = threadIdx.x;
    int w = t >> 5, l = t & 31;

    float km0 = conv_k[3], km1 = conv_k[4], km2 = conv_k[5];
    float s = bn_g[0] * rsqrtf(bn_rv[0] + 1e-5f);
    float bias = bn_b[0] - bn_rm[0] * s;

    for (int ch = w; ch < NCH; ch += 16) {
        const float* row = x_pe + ch * DD;
        float sum = 0.f;
        for (int i = l; i < DD; i += 32) {
            float left  = (i > 0)      ? row[i - 1] : 0.f;
            float mid   = row[i];
            float right = (i < DD - 1) ? row[i + 1] : 0.f;
            float conv = km0 * left + km1 * mid + km2 * right;
            float a = fmaxf(conv * s + bias, 0.f);
            g_xatt[ch * DD + i] = a;
            sum += a;
        }
        #pragma unroll
        for (int o = 16; o; o >>= 1) sum += __shfl_xor_sync(0xffffffffu, sum, o);
        if (l == 0) b1s[ch] = sum * (1.f / DD);
    }
    __syncthreads();

    if (t < NCH) {
        float v = b1s[t];
        int rank = 0, cnt = 0;
        float mx = -1e30f, mn = 1e30f;
        for (int j = 0; j < NCH; j++) {
            float u = b1s[j];
            rank += (u < v) || (u == v && j < t);
            cnt += (u <= 0.f);
            mx = fmaxf(mx, u);
            mn = fminf(mn, u);
        }
        int middle = (cnt == NCH) ? 0 : cnt;
        if (mx < 0.f || mn > 0.f) middle = 32;
        float ls = (float)middle, le = (float)(NCH - middle);
        float o;
        if (rank < middle) o = v - 1.f / (1.f + powf(ls, v));
        else               o = v + 1.f / (1.f + powf(le, -v));
        b2s[t] = o;
    }
    __syncthreads();

    if (t < 12) {
        float acc = 0.f;
        for (int c = 0; c < NCH; c++) acc += b2s[c] * fc_w1[c * 12 + t];
        hid[t] = fmaxf(acc, 0.f);
    }
    __syncthreads();

    if (t < NCH) {
        float acc = 0.f;
        #pragma unroll
        for (int k = 0; k < 12; k++) acc += hid[k] * fc_w2[k * NCH + t];
        csm[t] = 1.f / (1.f + expf(-acc));
    }
    __syncthreads();

    for (int i = t; i < NCH * DD; i += NT) g_xatt[i] *= csm[i / DD];
    for (int i = t; i < DD; i += NT) g_xatt[NCH * DD + i] = tokens[i];
}

// ---------------------------------------------------------------------------
// The single persistent kernel. 105 blocks x 512 threads.
// ---------------------------------------------------------------------------
__global__ void __launch_bounds__(NT, 1) k_all(
        const float* __restrict__ x, const float* __restrict__ tokens,
        const float* __restrict__ x_pe, const float* __restrict__ conv_k,
        const float* __restrict__ bn_g, const float* __restrict__ bn_b,
        const float* __restrict__ bn_rm, const float* __restrict__ bn_rv,
        const float* __restrict__ fc_w1, const float* __restrict__ fc_w2,
        const float* __restrict__ ln1_g, const float* __restrict__ ln1_b,
        const float* __restrict__ ln2_g, const float* __restrict__ ln2_b,
        const float* __restrict__ w_qkv, const float* __restrict__ w_out,
        const float* __restrict__ b_out,
        const float* __restrict__ ff_w1, const float* __restrict__ ff_b1,
        const float* __restrict__ ff_w2, const float* __restrict__ ff_b2,
        float* __restrict__ out) {
    __shared__ float sm[10400];
    int b = blockIdx.x;
    int t = threadIdx.x;

    // ===== Phase A: LN1 + QKV (blocks 0..103: 13 tiles x 8 chunks of 192 cols,
    //                2-way k-split); gate on block 104 =====
    if (b == 104) {
        gate_block(sm, x_pe, tokens, conv_k, bn_g, bn_b, bn_rm, bn_rv, fc_w1, fc_w2);
    } else {
        float* xs = sm;              // 980
        float* hs = sm + 980;        // 980
        float* smean = sm + 1960;
        float* sinv = sm + 1966;
        float* pA = sm + 1972;       // 192*5
        int tile = b >> 3, chunk = b & 7;
        int r0 = tile * 5;
        for (int i = t; i < 5 * DD; i += NT) xs[i] = x[r0 * DD + i];
        __syncthreads();
        ln_tile(xs, hs, ln1_g, ln1_b, smean, sinv);
        int cl = t % 192, ks = t / 192;   // ks in {0,1,2}; ks==2 idle
        int col = chunk * 192 + cl;
        float acc[5] = {0.f, 0.f, 0.f, 0.f, 0.f};
        if (ks < 2) {
            gemm5<14, 7>(w_qkv + (ks * 98) * 1536 + col, 1536, hs + ks * 98, DD, acc);
            if (ks == 1) {
                #pragma unroll
                for (int r = 0; r < 5; r++) pA[cl * 5 + r] = acc[r];
            }
        }
        __syncthreads();
        if (ks == 0) {
            #pragma unroll
            for (int r = 0; r < 5; r++)
                g_qkv[(r0 + r) * 1536 + col] = acc[r] + pA[cl * 5 + r];
        }
    }
    gsync();

    // ===== Phase B: attention + out-proj partial (13 tiles x 8 heads) =====
    if (b < 104) {
        float* skT = sm;             // 64 x 67 = 4288
        float* sv  = sm + 4288;      // 65 x 64 = 4160
        float* sq  = sm + 8448;      // 5 x 64
        float* sp  = sm + 8768;      // 5 x 66
        float* so2 = sm + 9098;      // 5 x 64
        float* pB  = sm + 9418;      // 196*5
        int tile = b >> 3, h = b & 7;
        int r0 = tile * 5;

        for (int i = t; i < SEQ * DH; i += NT) {
            int j = i >> 6, d = i & 63;
            skT[d * 67 + j] = g_qkv[j * 1536 + INNER + h * 64 + d];
            sv[i]           = g_qkv[j * 1536 + 2 * INNER + h * 64 + d];
        }
        if (t < 5 * DH) {
            int r = t >> 6, d = t & 63;
            sq[t] = g_qkv[(r0 + r) * 1536 + h * 64 + d];
        }
        __syncthreads();

        if (t < 5 * SEQ) {
            int i = t / SEQ, j = t - i * SEQ;
            float acc = 0.f;
            #pragma unroll
            for (int d = 0; d < DH; d++) acc += sq[i * 64 + d] * skT[d * 67 + j];
            sp[i * 66 + j] = acc * 0.125f;
        }
        __syncthreads();

        int w = t >> 5, l = t & 31;
        if (w < 5) {
            float mx = -1e30f;
            for (int j = l; j < SEQ; j += 32) mx = fmaxf(mx, sp[w * 66 + j]);
            #pragma unroll
            for (int o = 16; o; o >>= 1) mx = fmaxf(mx, __shfl_xor_sync(0xffffffffu, mx, o));
            float sum = 0.f;
            for (int j = l; j < SEQ; j += 32) {
                float p = expf(sp[w * 66 + j] - mx);
                sp[w * 66 + j] = p;
                sum += p;
            }
            #pragma unroll
            for (int o = 16; o; o >>= 1) sum += __shfl_xor_sync(0xffffffffu, sum, o);
            float inv = 1.f / sum;
            for (int j = l; j < SEQ; j += 32) sp[w * 66 + j] *= inv;
        }
        __syncthreads();

        if (t < 5 * DH) {
            int i = t >> 6, d = t & 63;
            float acc = 0.f;
            #pragma unroll 5
            for (int j = 0; j < SEQ; j++) acc += sp[i * 66 + j] * sv[j * 64 + d];
            so2[t] = acc;
        }
        __syncthreads();

        // out-proj partial for head slice [h*64,(h+1)*64), 2-way k-split
        int cl = t % DD, ks = t / DD;  // ks in {0,1,2}; ks==2 idle
        float acc[5] = {0.f, 0.f, 0.f, 0.f, 0.f};
        if (ks < 2) {
            gemm5<16, 2>(w_out + (h * 64 + ks * 32) * DD + cl, DD, so2 + ks * 32, 64, acc);
            if (ks == 1) {
                #pragma unroll
                for (int r = 0; r < 5; r++) pB[cl * 5 + r] = acc[r];
            }
        }
        __syncthreads();
        if (ks == 0) {
            #pragma unroll
            for (int r = 0; r < 5; r++)
                g_partC[(h * SEQ + r0 + r) * DD + cl] = acc[r] + pB[cl * 5 + r];
        }
    }
    gsync();

    // ===== Phase D: (fold C) build x2 rows, LN2 + FF1 + GELU + FF2-partial =====
    if (b < 104) {
        float* xs = sm;              // 980
        float* hs = sm + 980;        // 980
        float* smean = sm + 1960;
        float* sinv = sm + 1966;
        float* sg = sm + 1972;       // 5 x 98 = 490
        float* pD = sm + 2462;       // up to 3*490 / 980
        int tile = b >> 3, chunk = b & 7;
        int r0 = tile * 5;

        // x2 rows = x + xatt + b_out + sum_h partC
        for (int i = t; i < 5 * DD; i += NT) {
            int r = i / DD, c = i - r * DD;
            int gi = (r0 + r) * DD + c;
            float acc = x[gi] + g_xatt[gi] + b_out[c];
            #pragma unroll
            for (int hh = 0; hh < 8; hh++) acc += g_partC[(hh * SEQ + r0 + r) * DD + c];
            xs[i] = acc;
            if (chunk == 0) g_x2[gi] = acc;
        }
        __syncthreads();
        ln_tile(xs, hs, ln2_g, ln2_b, smean, sinv);

        // FF1 on 98 cols, 4-way k-split (49 each)
        {
            int cl = t % 98, ks = t / 98;  // 0..5; ks>=4 idle
            int col = chunk * 98 + cl;
            float acc[5] = {0.f, 0.f, 0.f, 0.f, 0.f};
            if (ks < 4) {
                gemm5<7, 7>(ff_w1 + (ks * 49) * MLP + col, MLP, hs + ks * 49, DD, acc);
                if (ks > 0) {
                    #pragma unroll
                    for (int r = 0; r < 5; r++) pD[(ks - 1) * 490 + cl * 5 + r] = acc[r];
                }
            }
            __syncthreads();
            if (ks == 0) {
                float bb = ff_b1[col];
                #pragma unroll
                for (int r = 0; r < 5; r++) {
                    float v = acc[r] + bb + pD[cl * 5 + r] + pD[490 + cl * 5 + r]
                              + pD[980 + cl * 5 + r];
                    sg[r * 98 + cl] = 0.5f * v * (1.f + erff(v * 0.70710678118654752f));
                }
            }
        }
        __syncthreads();

        // FF2 partial on this 98-slice of MLP, 2-way k-split (49 each)
        {
            int cl = t % DD, ks = t / DD;  // ks==2 idle
            float acc[5] = {0.f, 0.f, 0.f, 0.f, 0.f};
            if (ks < 2) {
                gemm5<7, 7>(ff_w2 + (chunk * 98 + ks * 49) * DD + cl, DD, sg + ks * 49, 98, acc);
                if (ks == 1) {
                    #pragma unroll
                    for (int r = 0; r < 5; r++) pD[cl * 5 + r] = acc[r];
                }
            }
            __syncthreads();
            if (ks == 0) {
                #pragma unroll
                for (int r = 0; r < 5; r++)
                    g_partE[(chunk * SEQ + r0 + r) * DD + cl] = acc[r] + pD[cl * 5 + r];
            }
        }
    }
    gsync();

    // ===== Phase E: reduce 8 partials + b2 + g_x2 -> out =====
    for (int i = b * NT + t; i < SEQ * DD; i += NBLK * NT) {
        int col = i % DD;
        float acc = g_x2[i] + ff_b2[col];
        #pragma unroll
        for (int ks = 0; ks < 8; ks++) acc += g_partE[ks * SEQ * DD + i];
        out[i] = acc;
    }
}

// ---------------------------------------------------------------------------
extern "C" void kernel_launch(void* const* d_in, const int* in_sizes, int n_in,
                              void* d_out, int out_size) {
    const float* x      = (const float*)d_in[0];
    const float* tokens = (const float*)d_in[1];
    const float* x_pe   = (const float*)d_in[2];
    const float* conv_k = (const float*)d_in[3];
    const float* bn_g   = (const float*)d_in[4];
    const float* bn_b   = (const float*)d_in[5];
    const float* bn_rm  = (const float*)d_in[6];
    const float* bn_rv  = (const float*)d_in[7];
    const float* fc_w1  = (const float*)d_in[8];
    const float* fc_w2  = (const float*)d_in[9];
    const float* ln1_g  = (const float*)d_in[10];
    const float* ln1_b  = (const float*)d_in[11];
    const float* ln2_g  = (const float*)d_in[12];
    const float* ln2_b  = (const float*)d_in[13];
    const float* w_qkv  = (const float*)d_in[14];
    const float* w_out  = (const float*)d_in[15];
    const float* b_out  = (const float*)d_in[16];
    const float* ff_w1  = (const float*)d_in[17];
    const float* ff_b1  = (const float*)d_in[18];
    const float* ff_w2  = (const float*)d_in[19];
    const float* ff_b2  = (const float*)d_in[20];
    float* out = (float*)d_out;

    k_all<<<NBLK, NT>>>(x, tokens, x_pe, conv_k, bn_g, bn_b, bn_rm, bn_rv,
                        fc_w1, fc_w2, ln1_g, ln1_b, ln2_g, ln2_b,
                        w_qkv, w_out, b_out, ff_w1, ff_b1, ff_w2, ff_b2, out);
}